// round 4
// baseline (speedup 1.0000x reference)
#include <cuda_runtime.h>
#include <math.h>

#define S 2048
#define D 768
#define H 12
#define HD 64
#define FF 3072
#define L 6
#define PAD_IDX 1
#define WIN 128
#define BQ 16
#define KWP 320            // padded window columns (5 chunks of 64); valid keys are first 272

// ---------------- scratch (static device globals: no allocation) ----------------
__device__ float g_x[S*D];
__device__ float g_q[S*D];
__device__ float g_k[S*D];
__device__ float g_v[S*D];
__device__ float g_o[S*D];
__device__ float g_t[S*D];
__device__ float g_f[S*FF];
__device__ int   g_pos[S];
__device__ float g_brel[H*257];   // bias per (head, rp+128), rp in [-128,128]

template<int ID>
__device__ __forceinline__ float* buf() {
    if constexpr (ID == 0) return g_x;
    else if constexpr (ID == 4) return g_o;
    else if constexpr (ID == 5) return g_t;
    else return g_f;   // ID == 6
}

// ---------------- positions (fairseq make_positions) ----------------
__global__ void pos_kernel(const int* __restrict__ tokens) {
    __shared__ int s_sum[256];
    int tid = threadIdx.x;
    int base = tid * 8;
    int np[8]; int tot = 0;
#pragma unroll
    for (int i = 0; i < 8; i++) { np[i] = (tokens[base+i] != PAD_IDX) ? 1 : 0; tot += np[i]; }
    s_sum[tid] = tot;
    __syncthreads();
    if (tid == 0) {
        int run = 0;
        for (int i = 0; i < 256; i++) { int v = s_sum[i]; s_sum[i] = run; run += v; }
    }
    __syncthreads();
    int run = s_sum[tid];
#pragma unroll
    for (int i = 0; i < 8; i++) {
        run += np[i];
        g_pos[base+i] = np[i] ? (PAD_IDX + run) : PAD_IDX;
    }
}

// ---------------- relative position bias table ----------------
__global__ void relbias_kernel(const float* __restrict__ rel_bias) {
    int j = threadIdx.x;
    if (j >= 257) return;
    int rp = j - 128;
    int n = -rp;
    int ret = (n < 0) ? 16 : 0;
    n = abs(n);
    int val;
    if (n < 8) val = n;
    else {
        val = 8 + (int)(logf((float)n / 8.0f) / logf(16.0f) * 8.0f);
        if (val > 15) val = 15;
    }
    int bucket = ret + val;
    for (int h = 0; h < H; h++)
        g_brel[h*257 + j] = rel_bias[bucket*H + h];
}

// ---------------- embedding ----------------
__global__ void embed_kernel(const int* __restrict__ tokens, const int* __restrict__ segs,
                             const float* __restrict__ emb, const float* __restrict__ pemb,
                             const float* __restrict__ semb) {
    int s = blockIdx.x;
    int c = threadIdx.x * 4;
    int tok = tokens[s];
    float4* dst = (float4*)&g_x[(size_t)s*D + c];
    if (tok == PAD_IDX) { *dst = make_float4(0.f,0.f,0.f,0.f); return; }
    float4 a = *(const float4*)&emb[(size_t)tok*D + c];
    float4 p = *(const float4*)&pemb[(size_t)g_pos[s]*D + c];
    float4 g = *(const float4*)&semb[(size_t)segs[s]*D + c];
    *dst = make_float4(a.x+p.x+g.x, a.y+p.y+g.y, a.z+p.z+g.z, a.w+p.w+g.w);
}

// ---------------- SGEMM core: C[M,N] = alpha*(A[M,K]@B[K,N] + bias), M=2048 ----------------
// BM=128, BN=64, BK=16, 128 threads, 8x8 micro-tile per thread
__device__ __forceinline__ void gemm_core(
    const float* __restrict__ A, const float* __restrict__ Bm,
    const float* __restrict__ bias, float* __restrict__ C,
    int N, int K, float alpha, int relu)
{
    __shared__ float As[16][128];
    __shared__ float Bs[16][64];
    int tid = threadIdx.x;
    int m0 = blockIdx.y * 128;
    int n0 = blockIdx.x * 64;
    int tx = tid & 7;
    int ty = tid >> 3;

    float acc[8][8];
#pragma unroll
    for (int i = 0; i < 8; i++)
#pragma unroll
        for (int j = 0; j < 8; j++) acc[i][j] = 0.f;

    int tA_r = tid >> 2;           // 0..31
    int tA_c = (tid & 3) << 2;     // 0,4,8,12

    for (int kt = 0; kt < K; kt += 16) {
#pragma unroll
        for (int i = 0; i < 4; i++) {
            int row = tA_r + (i << 5);
            float4 av = *(const float4*)(A + (size_t)(m0+row)*K + kt + tA_c);
            As[tA_c+0][row] = av.x; As[tA_c+1][row] = av.y;
            As[tA_c+2][row] = av.z; As[tA_c+3][row] = av.w;
        }
#pragma unroll
        for (int i = 0; i < 2; i++) {
            int idx = tid + (i << 7);
            int kr = idx >> 4;
            int c  = (idx & 15) << 2;
            *(float4*)&Bs[kr][c] = *(const float4*)(Bm + (size_t)(kt+kr)*N + n0 + c);
        }
        __syncthreads();
#pragma unroll
        for (int k = 0; k < 16; k++) {
            float a[8], b[8];
            *(float4*)&a[0] = *(float4*)&As[k][ty*8];
            *(float4*)&a[4] = *(float4*)&As[k][ty*8+4];
            *(float4*)&b[0] = *(float4*)&Bs[k][tx*8];
            *(float4*)&b[4] = *(float4*)&Bs[k][tx*8+4];
#pragma unroll
            for (int i = 0; i < 8; i++)
#pragma unroll
                for (int j = 0; j < 8; j++)
                    acc[i][j] = fmaf(a[i], b[j], acc[i][j]);
        }
        __syncthreads();
    }

    float bv[8];
#pragma unroll
    for (int j = 0; j < 8; j++) bv[j] = bias[n0 + tx*8 + j];
#pragma unroll
    for (int i = 0; i < 8; i++) {
        int row = m0 + ty*8 + i;
        float out[8];
#pragma unroll
        for (int j = 0; j < 8; j++) {
            float v = (acc[i][j] + bv[j]) * alpha;
            if (relu) v = fmaxf(v, 0.f);
            out[j] = v;
        }
        *(float4*)(C + (size_t)row*N + n0 + tx*8)     = *(float4*)&out[0];
        *(float4*)(C + (size_t)row*N + n0 + tx*8 + 4) = *(float4*)&out[4];
    }
}

template<int AID, int CID>
__global__ __launch_bounds__(128) void gemm_tpl(const float* __restrict__ Bm,
    const float* __restrict__ bias, int N, int K, float alpha, int relu)
{
    gemm_core(buf<AID>(), Bm, bias, buf<CID>(), N, K, alpha, relu);
}

__global__ __launch_bounds__(128) void gemm_qkv(
    const float* __restrict__ Wq, const float* __restrict__ Wk, const float* __restrict__ Wv,
    const float* __restrict__ bq, const float* __restrict__ bk, const float* __restrict__ bv)
{
    const float* Bm; const float* bias; float* C; float alpha = 1.f;
    if (blockIdx.z == 0)      { Bm = Wq; bias = bq; C = g_q; alpha = 0.125f; } // 1/sqrt(64)
    else if (blockIdx.z == 1) { Bm = Wk; bias = bk; C = g_k; }
    else                      { Bm = Wv; bias = bv; C = g_v; }
    gemm_core(g_x, Bm, bias, C, D, D, alpha, 0);
}

// ---------------- fused windowed attention ----------------
// block = (q-tile of 16, head). Keys kstart..kstart+319 (padded), valid window = 272.
__global__ __launch_bounds__(256) void attn_kernel(const int* __restrict__ tokens) {
    __shared__ float Qs[BQ][HD];
    __shared__ float KVs[64][65];        // stride 65: conflict-free column access
    __shared__ float Sc[BQ][KWP];
    int h   = blockIdx.y;
    int q0  = blockIdx.x * BQ;
    int tid = threadIdx.x;
    int kstart = q0 - WIN;

    {
        int i = tid >> 4;
        int c = (tid & 15) << 2;
        *(float4*)&Qs[i][c] = *(const float4*)(g_q + (size_t)(q0+i)*D + h*HD + c);
    }

    int jj = tid & 63;
    int i0 = (tid >> 6) << 2;

    // ---- scores ----
    for (int c0 = 0; c0 < KWP; c0 += 64) {
        __syncthreads();
        for (int e = tid; e < 64*64; e += 256) {
            int r = e >> 6, dd = e & 63;
            int key = kstart + c0 + r;
            KVs[r][dd] = (key >= 0 && key < S) ? g_k[(size_t)key*D + h*HD + dd] : 0.f;
        }
        __syncthreads();
        float a0=0.f, a1=0.f, a2=0.f, a3=0.f;
#pragma unroll 16
        for (int dd = 0; dd < 64; dd++) {
            float kv = KVs[jj][dd];
            a0 = fmaf(Qs[i0+0][dd], kv, a0);
            a1 = fmaf(Qs[i0+1][dd], kv, a1);
            a2 = fmaf(Qs[i0+2][dd], kv, a2);
            a3 = fmaf(Qs[i0+3][dd], kv, a3);
        }
        int key = kstart + c0 + jj;
        bool inr = (key >= 0 && key < S);
        float padp = (inr && tokens[key] == PAD_IDX) ? -1e30f : 0.f;
        float av[4] = {a0, a1, a2, a3};
#pragma unroll
        for (int r = 0; r < 4; r++) {
            int rp = key - (q0 + i0 + r);
            float sc;
            if (!inr || rp < -WIN || rp > WIN) sc = -3.0e38f;
            else sc = av[r] + g_brel[h*257 + rp + WIN] + padp;
            Sc[i0+r][c0+jj] = sc;
        }
    }
    __syncthreads();

    // ---- softmax: 8 warps x 2 rows ----
    {
        int warp = tid >> 5, lane = tid & 31;
#pragma unroll
        for (int rr = 0; rr < 2; rr++) {
            int i = warp*2 + rr;
            float m = -3.4e38f;
            for (int j = lane; j < KWP; j += 32) m = fmaxf(m, Sc[i][j]);
#pragma unroll
            for (int off = 16; off; off >>= 1) m = fmaxf(m, __shfl_xor_sync(0xffffffffu, m, off));
            float ssum = 0.f;
            for (int j = lane; j < KWP; j += 32) {
                float e = expf(Sc[i][j] - m);
                Sc[i][j] = e;
                ssum += e;
            }
#pragma unroll
            for (int off = 16; off; off >>= 1) ssum += __shfl_xor_sync(0xffffffffu, ssum, off);
            float inv = 1.f / ssum;
            for (int j = lane; j < KWP; j += 32) Sc[i][j] *= inv;
        }
    }
    __syncthreads();

    // ---- P @ V ----
    int dd = tid & 63;
    float o0=0.f, o1=0.f, o2=0.f, o3=0.f;
    for (int c0 = 0; c0 < KWP; c0 += 64) {
        __syncthreads();
        for (int e = tid; e < 64*64; e += 256) {
            int r = e >> 6, d2 = e & 63;
            int key = kstart + c0 + r;
            KVs[r][d2] = (key >= 0 && key < S) ? g_v[(size_t)key*D + h*HD + d2] : 0.f;
        }
        __syncthreads();
#pragma unroll 16
        for (int j = 0; j < 64; j++) {
            float vv = KVs[j][dd];
            o0 = fmaf(Sc[i0+0][c0+j], vv, o0);
            o1 = fmaf(Sc[i0+1][c0+j], vv, o1);
            o2 = fmaf(Sc[i0+2][c0+j], vv, o2);
            o3 = fmaf(Sc[i0+3][c0+j], vv, o3);
        }
    }
    g_o[(size_t)(q0+i0+0)*D + h*HD + dd] = o0;
    g_o[(size_t)(q0+i0+1)*D + h*HD + dd] = o1;
    g_o[(size_t)(q0+i0+2)*D + h*HD + dd] = o2;
    g_o[(size_t)(q0+i0+3)*D + h*HD + dd] = o3;
}

// ---------------- residual + LayerNorm (reads g_x, g_t; writes g_x or d_out) ----------------
template<bool TO_OUT>
__global__ __launch_bounds__(256) void ln_kernel(const float* __restrict__ sc,
    const float* __restrict__ bb, float* __restrict__ outp)
{
    float* dst = TO_OUT ? outp : g_x;
    __shared__ float red[256];
    __shared__ float sh_m, sh_r;
    int row = blockIdx.x, tid = threadIdx.x;
    size_t base = (size_t)row * D;
    float v0 = g_x[base + tid      ] + g_t[base + tid      ];
    float v1 = g_x[base + tid + 256] + g_t[base + tid + 256];
    float v2 = g_x[base + tid + 512] + g_t[base + tid + 512];
    red[tid] = v0 + v1 + v2;
    __syncthreads();
#pragma unroll
    for (int o2 = 128; o2; o2 >>= 1) { if (tid < o2) red[tid] += red[tid + o2]; __syncthreads(); }
    if (tid == 0) sh_m = red[0] * (1.f / 768.f);
    __syncthreads();
    float m = sh_m;
    float d0 = v0 - m, d1 = v1 - m, d2 = v2 - m;
    red[tid] = d0*d0 + d1*d1 + d2*d2;
    __syncthreads();
#pragma unroll
    for (int o2 = 128; o2; o2 >>= 1) { if (tid < o2) red[tid] += red[tid + o2]; __syncthreads(); }
    if (tid == 0) sh_r = rsqrtf(red[0] * (1.f / 768.f) + 1e-5f);
    __syncthreads();
    float r = sh_r;
    dst[base + tid      ] = d0 * r * sc[tid      ] + bb[tid      ];
    dst[base + tid + 256] = d1 * r * sc[tid + 256] + bb[tid + 256];
    dst[base + tid + 512] = d2 * r * sc[tid + 512] + bb[tid + 512];
}

// ---------------- driver ----------------
extern "C" void kernel_launch(void* const* d_in, const int* in_sizes, int n_in,
                              void* d_out, int out_size)
{
    const int*   tokens = (const int*)  d_in[0];
    const int*   segs   = (const int*)  d_in[1];
    const float* emb    = (const float*)d_in[2];
    const float* pemb   = (const float*)d_in[3];
    const float* semb   = (const float*)d_in[4];
    const float* relb   = (const float*)d_in[5];
    const float* Wq     = (const float*)d_in[6];
    const float* bq     = (const float*)d_in[7];
    const float* Wk     = (const float*)d_in[8];
    const float* bk     = (const float*)d_in[9];
    const float* Wv     = (const float*)d_in[10];
    const float* bv     = (const float*)d_in[11];
    const float* Wo     = (const float*)d_in[12];
    const float* bo     = (const float*)d_in[13];
    const float* ln1s   = (const float*)d_in[14];
    const float* ln1b   = (const float*)d_in[15];
    const float* W1     = (const float*)d_in[16];
    const float* b1     = (const float*)d_in[17];
    const float* W2     = (const float*)d_in[18];
    const float* b2     = (const float*)d_in[19];
    const float* ln2s   = (const float*)d_in[20];
    const float* ln2b   = (const float*)d_in[21];
    float* out = (float*)d_out;

    dim3 g768(D/64, S/128);        // (12, 16)
    dim3 gFF(FF/64, S/128);        // (48, 16)
    dim3 gqkv(D/64, S/128, 3);     // (12, 16, 3)
    dim3 gattn(S/BQ, H);           // (128, 12)

    pos_kernel<<<1, 256>>>(tokens);
    relbias_kernel<<<1, 288>>>(relb);
    embed_kernel<<<S, 192>>>(tokens, segs, emb, pemb, semb);

    for (int l = 0; l < L; l++) {
        size_t wdd = (size_t)l * D * D;
        gemm_qkv<<<gqkv, 128>>>(Wq + wdd, Wk + wdd, Wv + wdd,
                                bq + l*D, bk + l*D, bv + l*D);
        attn_kernel<<<gattn, 256>>>(tokens);
        gemm_tpl<4,5><<<g768, 128>>>(Wo + wdd, bo + l*D, D, D, 1.f, 0);
        ln_kernel<false><<<S, 256>>>(ln1s + l*D, ln1b + l*D, nullptr);
        gemm_tpl<0,6><<<gFF, 128>>>(W1 + (size_t)l*D*FF, b1 + (size_t)l*FF, FF, D, 1.f, 1);
        gemm_tpl<6,5><<<g768, 128>>>(W2 + (size_t)l*FF*D, b2 + l*D, D, FF, 1.f, 0);
        if (l == L-1) ln_kernel<true ><<<S, 256>>>(ln2s + l*D, ln2b + l*D, out);
        else          ln_kernel<false><<<S, 256>>>(ln2s + l*D, ln2b + l*D, nullptr);
    }
}

// round 5
// speedup vs baseline: 1.0015x; 1.0015x over previous
#include <cuda_runtime.h>
#include <math.h>

#define S 2048
#define D 768
#define H 12
#define HD 64
#define FF 3072
#define L 6
#define PAD_IDX 1
#define WIN 128
#define BQ 16
#define KWP 320            // padded window columns (5 chunks of 64); valid keys are first 272

// ---------------- scratch (static device globals: no allocation) ----------------
__device__ float g_x[S*D];
__device__ float g_q[S*D];
__device__ float g_k[S*D];
__device__ float g_v[S*D];
__device__ float g_o[S*D];
__device__ float g_t[S*D];
__device__ float g_f[S*FF];
__device__ int   g_pos[S];
__device__ float g_brel[H*257];   // bias per (head, rp+128), rp in [-128,128]

template<int ID>
__device__ __forceinline__ float* buf() {
    if constexpr (ID == 0) return g_x;
    else if constexpr (ID == 4) return g_o;
    else if constexpr (ID == 5) return g_t;
    else return g_f;   // ID == 6
}

// ---------------- positions (fairseq make_positions) ----------------
__global__ void pos_kernel(const int* __restrict__ tokens) {
    __shared__ int s_sum[256];
    int tid = threadIdx.x;
    int base = tid * 8;
    int np[8]; int tot = 0;
#pragma unroll
    for (int i = 0; i < 8; i++) { np[i] = (tokens[base+i] != PAD_IDX) ? 1 : 0; tot += np[i]; }
    s_sum[tid] = tot;
    __syncthreads();
    if (tid == 0) {
        int run = 0;
        for (int i = 0; i < 256; i++) { int v = s_sum[i]; s_sum[i] = run; run += v; }
    }
    __syncthreads();
    int run = s_sum[tid];
#pragma unroll
    for (int i = 0; i < 8; i++) {
        run += np[i];
        g_pos[base+i] = np[i] ? (PAD_IDX + run) : PAD_IDX;
    }
}

// ---------------- relative position bias table ----------------
__global__ void relbias_kernel(const float* __restrict__ rel_bias) {
    int j = threadIdx.x;
    if (j >= 257) return;
    int rp = j - 128;
    int n = -rp;
    int ret = (n < 0) ? 16 : 0;
    n = abs(n);
    int val;
    if (n < 8) val = n;
    else {
        val = 8 + (int)(logf((float)n / 8.0f) / logf(16.0f) * 8.0f);
        if (val > 15) val = 15;
    }
    int bucket = ret + val;
    for (int h = 0; h < H; h++)
        g_brel[h*257 + j] = rel_bias[bucket*H + h];
}

// ---------------- embedding ----------------
__global__ void embed_kernel(const int* __restrict__ tokens, const int* __restrict__ segs,
                             const float* __restrict__ emb, const float* __restrict__ pemb,
                             const float* __restrict__ semb) {
    int s = blockIdx.x;
    int c = threadIdx.x * 4;
    int tok = tokens[s];
    float4* dst = (float4*)&g_x[(size_t)s*D + c];
    if (tok == PAD_IDX) { *dst = make_float4(0.f,0.f,0.f,0.f); return; }
    float4 a = *(const float4*)&emb[(size_t)tok*D + c];
    float4 p = *(const float4*)&pemb[(size_t)g_pos[s]*D + c];
    float4 g = *(const float4*)&semb[(size_t)segs[s]*D + c];
    *dst = make_float4(a.x+p.x+g.x, a.y+p.y+g.y, a.z+p.z+g.z, a.w+p.w+g.w);
}

// ---------------- SGEMM core: C[M,N] = alpha*(A[M,K]@B[K,N] + bias), M=2048 ----------------
// BM=128, BN=64, BK=16, 128 threads, 8x8 micro-tile per thread
__device__ __forceinline__ void gemm_core(
    const float* __restrict__ A, const float* __restrict__ Bm,
    const float* __restrict__ bias, float* __restrict__ C,
    int N, int K, float alpha, int relu)
{
    __shared__ float As[16][128];
    __shared__ float Bs[16][64];
    int tid = threadIdx.x;
    int m0 = blockIdx.y * 128;
    int n0 = blockIdx.x * 64;
    int tx = tid & 7;
    int ty = tid >> 3;

    float acc[8][8];
#pragma unroll
    for (int i = 0; i < 8; i++)
#pragma unroll
        for (int j = 0; j < 8; j++) acc[i][j] = 0.f;

    int tA_r = tid >> 2;           // 0..31
    int tA_c = (tid & 3) << 2;     // 0,4,8,12

    for (int kt = 0; kt < K; kt += 16) {
#pragma unroll
        for (int i = 0; i < 4; i++) {
            int row = tA_r + (i << 5);
            float4 av = *(const float4*)(A + (size_t)(m0+row)*K + kt + tA_c);
            As[tA_c+0][row] = av.x; As[tA_c+1][row] = av.y;
            As[tA_c+2][row] = av.z; As[tA_c+3][row] = av.w;
        }
#pragma unroll
        for (int i = 0; i < 2; i++) {
            int idx = tid + (i << 7);
            int kr = idx >> 4;
            int c  = (idx & 15) << 2;
            *(float4*)&Bs[kr][c] = *(const float4*)(Bm + (size_t)(kt+kr)*N + n0 + c);
        }
        __syncthreads();
#pragma unroll
        for (int k = 0; k < 16; k++) {
            float a[8], b[8];
            *(float4*)&a[0] = *(float4*)&As[k][ty*8];
            *(float4*)&a[4] = *(float4*)&As[k][ty*8+4];
            *(float4*)&b[0] = *(float4*)&Bs[k][tx*8];
            *(float4*)&b[4] = *(float4*)&Bs[k][tx*8+4];
#pragma unroll
            for (int i = 0; i < 8; i++)
#pragma unroll
                for (int j = 0; j < 8; j++)
                    acc[i][j] = fmaf(a[i], b[j], acc[i][j]);
        }
        __syncthreads();
    }

    float bv[8];
#pragma unroll
    for (int j = 0; j < 8; j++) bv[j] = bias[n0 + tx*8 + j];
#pragma unroll
    for (int i = 0; i < 8; i++) {
        int row = m0 + ty*8 + i;
        float out[8];
#pragma unroll
        for (int j = 0; j < 8; j++) {
            float v = (acc[i][j] + bv[j]) * alpha;
            if (relu) v = fmaxf(v, 0.f);
            out[j] = v;
        }
        *(float4*)(C + (size_t)row*N + n0 + tx*8)     = *(float4*)&out[0];
        *(float4*)(C + (size_t)row*N + n0 + tx*8 + 4) = *(float4*)&out[4];
    }
}

template<int AID, int CID>
__global__ __launch_bounds__(128) void gemm_tpl(const float* __restrict__ Bm,
    const float* __restrict__ bias, int N, int K, float alpha, int relu)
{
    gemm_core(buf<AID>(), Bm, bias, buf<CID>(), N, K, alpha, relu);
}

__global__ __launch_bounds__(128) void gemm_qkv(
    const float* __restrict__ Wq, const float* __restrict__ Wk, const float* __restrict__ Wv,
    const float* __restrict__ bq, const float* __restrict__ bk, const float* __restrict__ bv)
{
    const float* Bm; const float* bias; float* C; float alpha = 1.f;
    if (blockIdx.z == 0)      { Bm = Wq; bias = bq; C = g_q; alpha = 0.125f; } // 1/sqrt(64)
    else if (blockIdx.z == 1) { Bm = Wk; bias = bk; C = g_k; }
    else                      { Bm = Wv; bias = bv; C = g_v; }
    gemm_core(g_x, Bm, bias, C, D, D, alpha, 0);
}

// ---------------- fused windowed attention ----------------
// block = (q-tile of 16, head). Keys kstart..kstart+319 (padded), valid window = 272.
__global__ __launch_bounds__(256) void attn_kernel(const int* __restrict__ tokens) {
    __shared__ float Qs[BQ][HD];
    __shared__ float KVs[64][65];        // stride 65: conflict-free column access
    __shared__ float Sc[BQ][KWP];
    int h   = blockIdx.y;
    int q0  = blockIdx.x * BQ;
    int tid = threadIdx.x;
    int kstart = q0 - WIN;

    {
        int i = tid >> 4;
        int c = (tid & 15) << 2;
        *(float4*)&Qs[i][c] = *(const float4*)(g_q + (size_t)(q0+i)*D + h*HD + c);
    }

    int jj = tid & 63;
    int i0 = (tid >> 6) << 2;

    // ---- scores ----
    for (int c0 = 0; c0 < KWP; c0 += 64) {
        __syncthreads();
        for (int e = tid; e < 64*64; e += 256) {
            int r = e >> 6, dd = e & 63;
            int key = kstart + c0 + r;
            KVs[r][dd] = (key >= 0 && key < S) ? g_k[(size_t)key*D + h*HD + dd] : 0.f;
        }
        __syncthreads();
        float a0=0.f, a1=0.f, a2=0.f, a3=0.f;
#pragma unroll 16
        for (int dd = 0; dd < 64; dd++) {
            float kv = KVs[jj][dd];
            a0 = fmaf(Qs[i0+0][dd], kv, a0);
            a1 = fmaf(Qs[i0+1][dd], kv, a1);
            a2 = fmaf(Qs[i0+2][dd], kv, a2);
            a3 = fmaf(Qs[i0+3][dd], kv, a3);
        }
        int key = kstart + c0 + jj;
        bool inr = (key >= 0 && key < S);
        float padp = (inr && tokens[key] == PAD_IDX) ? -1e30f : 0.f;
        float av[4] = {a0, a1, a2, a3};
#pragma unroll
        for (int r = 0; r < 4; r++) {
            int rp = key - (q0 + i0 + r);
            float sc;
            if (!inr || rp < -WIN || rp > WIN) sc = -3.0e38f;
            else sc = av[r] + g_brel[h*257 + rp + WIN] + padp;
            Sc[i0+r][c0+jj] = sc;
        }
    }
    __syncthreads();

    // ---- softmax: 8 warps x 2 rows ----
    {
        int warp = tid >> 5, lane = tid & 31;
#pragma unroll
        for (int rr = 0; rr < 2; rr++) {
            int i = warp*2 + rr;
            float m = -3.4e38f;
            for (int j = lane; j < KWP; j += 32) m = fmaxf(m, Sc[i][j]);
#pragma unroll
            for (int off = 16; off; off >>= 1) m = fmaxf(m, __shfl_xor_sync(0xffffffffu, m, off));
            float ssum = 0.f;
            for (int j = lane; j < KWP; j += 32) {
                float e = expf(Sc[i][j] - m);
                Sc[i][j] = e;
                ssum += e;
            }
#pragma unroll
            for (int off = 16; off; off >>= 1) ssum += __shfl_xor_sync(0xffffffffu, ssum, off);
            float inv = 1.f / ssum;
            for (int j = lane; j < KWP; j += 32) Sc[i][j] *= inv;
        }
    }
    __syncthreads();

    // ---- P @ V ----
    int dd = tid & 63;
    float o0=0.f, o1=0.f, o2=0.f, o3=0.f;
    for (int c0 = 0; c0 < KWP; c0 += 64) {
        __syncthreads();
        for (int e = tid; e < 64*64; e += 256) {
            int r = e >> 6, d2 = e & 63;
            int key = kstart + c0 + r;
            KVs[r][d2] = (key >= 0 && key < S) ? g_v[(size_t)key*D + h*HD + d2] : 0.f;
        }
        __syncthreads();
#pragma unroll 16
        for (int j = 0; j < 64; j++) {
            float vv = KVs[j][dd];
            o0 = fmaf(Sc[i0+0][c0+j], vv, o0);
            o1 = fmaf(Sc[i0+1][c0+j], vv, o1);
            o2 = fmaf(Sc[i0+2][c0+j], vv, o2);
            o3 = fmaf(Sc[i0+3][c0+j], vv, o3);
        }
    }
    g_o[(size_t)(q0+i0+0)*D + h*HD + dd] = o0;
    g_o[(size_t)(q0+i0+1)*D + h*HD + dd] = o1;
    g_o[(size_t)(q0+i0+2)*D + h*HD + dd] = o2;
    g_o[(size_t)(q0+i0+3)*D + h*HD + dd] = o3;
}

// ---------------- residual + LayerNorm (reads g_x, g_t; writes g_x or d_out) ----------------
template<bool TO_OUT>
__global__ __launch_bounds__(256) void ln_kernel(const float* __restrict__ sc,
    const float* __restrict__ bb, float* __restrict__ outp)
{
    float* dst = TO_OUT ? outp : g_x;
    __shared__ float red[256];
    __shared__ float sh_m, sh_r;
    int row = blockIdx.x, tid = threadIdx.x;
    size_t base = (size_t)row * D;
    float v0 = g_x[base + tid      ] + g_t[base + tid      ];
    float v1 = g_x[base + tid + 256] + g_t[base + tid + 256];
    float v2 = g_x[base + tid + 512] + g_t[base + tid + 512];
    red[tid] = v0 + v1 + v2;
    __syncthreads();
#pragma unroll
    for (int o2 = 128; o2; o2 >>= 1) { if (tid < o2) red[tid] += red[tid + o2]; __syncthreads(); }
    if (tid == 0) sh_m = red[0] * (1.f / 768.f);
    __syncthreads();
    float m = sh_m;
    float d0 = v0 - m, d1 = v1 - m, d2 = v2 - m;
    red[tid] = d0*d0 + d1*d1 + d2*d2;
    __syncthreads();
#pragma unroll
    for (int o2 = 128; o2; o2 >>= 1) { if (tid < o2) red[tid] += red[tid + o2]; __syncthreads(); }
    if (tid == 0) sh_r = rsqrtf(red[0] * (1.f / 768.f) + 1e-5f);
    __syncthreads();
    float r = sh_r;
    dst[base + tid      ] = d0 * r * sc[tid      ] + bb[tid      ];
    dst[base + tid + 256] = d1 * r * sc[tid + 256] + bb[tid + 256];
    dst[base + tid + 512] = d2 * r * sc[tid + 512] + bb[tid + 512];
}

// ---------------- driver ----------------
extern "C" void kernel_launch(void* const* d_in, const int* in_sizes, int n_in,
                              void* d_out, int out_size)
{
    const int*   tokens = (const int*)  d_in[0];
    const int*   segs   = (const int*)  d_in[1];
    const float* emb    = (const float*)d_in[2];
    const float* pemb   = (const float*)d_in[3];
    const float* semb   = (const float*)d_in[4];
    const float* relb   = (const float*)d_in[5];
    const float* Wq     = (const float*)d_in[6];
    const float* bq     = (const float*)d_in[7];
    const float* Wk     = (const float*)d_in[8];
    const float* bk     = (const float*)d_in[9];
    const float* Wv     = (const float*)d_in[10];
    const float* bv     = (const float*)d_in[11];
    const float* Wo     = (const float*)d_in[12];
    const float* bo     = (const float*)d_in[13];
    const float* ln1s   = (const float*)d_in[14];
    const float* ln1b   = (const float*)d_in[15];
    const float* W1     = (const float*)d_in[16];
    const float* b1     = (const float*)d_in[17];
    const float* W2     = (const float*)d_in[18];
    const float* b2     = (const float*)d_in[19];
    const float* ln2s   = (const float*)d_in[20];
    const float* ln2b   = (const float*)d_in[21];
    float* out = (float*)d_out;

    dim3 g768(D/64, S/128);        // (12, 16)
    dim3 gFF(FF/64, S/128);        // (48, 16)
    dim3 gqkv(D/64, S/128, 3);     // (12, 16, 3)
    dim3 gattn(S/BQ, H);           // (128, 12)

    pos_kernel<<<1, 256>>>(tokens);
    relbias_kernel<<<1, 288>>>(relb);
    embed_kernel<<<S, 192>>>(tokens, segs, emb, pemb, semb);

    for (int l = 0; l < L; l++) {
        size_t wdd = (size_t)l * D * D;
        gemm_qkv<<<gqkv, 128>>>(Wq + wdd, Wk + wdd, Wv + wdd,
                                bq + l*D, bk + l*D, bv + l*D);
        attn_kernel<<<gattn, 256>>>(tokens);
        gemm_tpl<4,5><<<g768, 128>>>(Wo + wdd, bo + l*D, D, D, 1.f, 0);
        ln_kernel<false><<<S, 256>>>(ln1s + l*D, ln1b + l*D, nullptr);
        gemm_tpl<0,6><<<gFF, 128>>>(W1 + (size_t)l*D*FF, b1 + (size_t)l*FF, FF, D, 1.f, 1);
        gemm_tpl<6,5><<<g768, 128>>>(W2 + (size_t)l*FF*D, b2 + l*D, D, FF, 1.f, 0);
        if (l == L-1) ln_kernel<true ><<<S, 256>>>(ln2s + l*D, ln2b + l*D, out);
        else          ln_kernel<false><<<S, 256>>>(ln2s + l*D, ln2b + l*D, nullptr);
    }
}